// round 1
// baseline (speedup 1.0000x reference)
#include <cuda_runtime.h>
#include <math.h>

// Problem constants
#define Bc   8
#define Nc   512
#define Tc   64
#define NINc 64
#define NEc  128
#define NHc  128
#define Rc   (Bc * Nc)   // 4096 rows total

// ---------------- scratch (device globals; no allocation allowed) ----------
__device__ float g_dinv[Rc];                 // 16 KB
__device__ float g_An[Bc * Nc * Nc];         // 8 MB   normalized adjacency
__device__ float g_es[Rc * NEc];             // 2 MB   static per-node embedding
__device__ float g_h[2][Rc * NHc];           // 4 MB   double-buffered hidden state
__device__ float g_c[Rc * NHc];              // 2 MB   cell state
__device__ float g_Hagg[Rc * NHc];           // 2 MB   H = An @ h
__device__ float g_G[Rc * 4 * NHc];          // 8 MB   gate pre-activations [i f g o]
__device__ float g_Xi[Rc * NINc];            // 1 MB   running output accumulator
__device__ float g_Wbig[384 * 512];          // 768 KB fused gate weight
__device__ float g_bbig[512];

// ---------------------------------------------------------------------------
// dinv[b,i] = rsqrt(rowsum(A[b,i,:]))  (0 if rowsum <= 0)
// ---------------------------------------------------------------------------
__global__ void k_dinv(const float* __restrict__ A) {
    int row = blockIdx.x;                       // b*N + i
    const float* arow = A + (size_t)row * Nc;
    float s = 0.f;
    for (int j = threadIdx.x; j < Nc; j += blockDim.x) s += arow[j];
    __shared__ float sh[128];
    sh[threadIdx.x] = s;
    __syncthreads();
    for (int off = 64; off > 0; off >>= 1) {
        if (threadIdx.x < off) sh[threadIdx.x] += sh[threadIdx.x + off];
        __syncthreads();
    }
    if (threadIdx.x == 0) {
        float d = sh[0];
        g_dinv[row] = (d > 0.f) ? rsqrtf(d) : 0.f;
    }
}

// ---------------------------------------------------------------------------
// An[b,i,j] = A[b,i,j] * dinv[b,i] * dinv[b,j]
// ---------------------------------------------------------------------------
__global__ void k_an(const float* __restrict__ A) {
    int idx = blockIdx.x * blockDim.x + threadIdx.x;   // float4 index
    int e = idx * 4;
    int b   = e >> 18;            // 512*512 = 262144 per batch
    int rem = e & 262143;
    int i   = rem >> 9;
    int j   = rem & 511;
    float4 a = *(const float4*)(A + (size_t)e);
    float di = g_dinv[b * 512 + i];
    const float* dj = g_dinv + b * 512 + j;
    a.x *= di * dj[0];
    a.y *= di * dj[1];
    a.z *= di * dj[2];
    a.w *= di * dj[3];
    *(float4*)(g_An + (size_t)e) = a;
}

// ---------------------------------------------------------------------------
// Build Wbig (384 x 512) and bbig (512):
//   rows   0:128 -> Wi_g[0:128,:]             (es part)
//   rows 128:256 -> Wpe @ Wi_g[128:256,:]     (H part; folds eh = H@Wpe + bpe)
//   rows 256:384 -> Wh_g                      (h part)
//   bbig = bi + bh + bpe @ Wi_g[128:256,:]
// One block per output column gcol = g*128 + j, 128 threads (one per k-row).
// ---------------------------------------------------------------------------
__global__ void k_prep(const float* __restrict__ Wii, const float* __restrict__ bii,
                       const float* __restrict__ Whi, const float* __restrict__ bhi,
                       const float* __restrict__ Wif, const float* __restrict__ bif_,
                       const float* __restrict__ Whf, const float* __restrict__ bhf,
                       const float* __restrict__ Wig, const float* __restrict__ big_,
                       const float* __restrict__ Whg, const float* __restrict__ bhg,
                       const float* __restrict__ Wio, const float* __restrict__ bio,
                       const float* __restrict__ Who, const float* __restrict__ bho,
                       const float* __restrict__ Wpe, const float* __restrict__ bpe) {
    int gcol = blockIdx.x;
    int g = gcol >> 7;
    int j = gcol & 127;
    int t = threadIdx.x;
    const float* Wi = (g == 0) ? Wii : (g == 1) ? Wif : (g == 2) ? Wig : Wio;
    const float* Wh = (g == 0) ? Whi : (g == 1) ? Whf : (g == 2) ? Whg : Who;
    const float* bi = (g == 0) ? bii : (g == 1) ? bif_ : (g == 2) ? big_ : bio;
    const float* bh = (g == 0) ? bhi : (g == 1) ? bhf : (g == 2) ? bhg : bho;

    __shared__ float wcol[128];                 // Wi_g[128+m, j]
    wcol[t] = Wi[(128 + t) * 128 + j];
    __syncthreads();

    g_Wbig[t * 512 + gcol]         = Wi[t * 128 + j];
    g_Wbig[(256 + t) * 512 + gcol] = Wh[t * 128 + j];

    float acc = 0.f;
    const float* wpet = Wpe + t * 128;
#pragma unroll 8
    for (int m = 0; m < 128; m++) acc += wpet[m] * wcol[m];
    g_Wbig[(128 + t) * 512 + gcol] = acc;

    if (t == 0) {
        float ba = bi[j] + bh[j];
        for (int m = 0; m < 128; m++) ba += bpe[m] * wcol[m];
        g_bbig[gcol] = ba;
    }
}

// ---------------------------------------------------------------------------
// Init: es = X0 @ Wse + bse ; h0 = c0 = 0 ; Xi = X0 ; out[:, :, 0, :] = X0
// One block per row (4096), 128 threads.
// ---------------------------------------------------------------------------
__global__ void k_init(const float* __restrict__ X, const float* __restrict__ Wse,
                       const float* __restrict__ bse, float* __restrict__ out) {
    int row = blockIdx.x;
    int t = threadIdx.x;
    __shared__ float x0[64];
    if (t < 64) {
        float v = X[(size_t)row * 4096 + t];     // X[b,n,0,t]
        x0[t] = v;
        g_Xi[row * 64 + t] = v;
        out[(size_t)row * 4096 + t] = v;          // out[b,n,0,t]
    }
    __syncthreads();
    float acc = bse[t];
#pragma unroll 8
    for (int k = 0; k < 64; k++) acc += x0[k] * Wse[k * 128 + t];
    g_es[row * 128 + t] = acc;
    g_h[0][(size_t)row * 128 + t] = 0.f;
    g_c[row * 128 + t] = 0.f;
}

// ---------------------------------------------------------------------------
// H = An @ h_prev   batched GEMM (per batch 512x512 @ 512x128)
// 64x64 tiles, 256 threads, 4x4 microtile, k-chunks of 16.
// grid = 8 batches * 8 mtiles * 2 ntiles = 128 blocks
// ---------------------------------------------------------------------------
__global__ void k_gemmH(int hin) {
    const float* __restrict__ h = g_h[hin];
    int bx = blockIdx.x;
    int b  = bx >> 4;
    int rem = bx & 15;
    int m0 = (rem >> 1) * 64;
    int n0 = (rem & 1) * 64;
    const float* Ab = g_An + (size_t)b * Nc * Nc;
    const float* Bb = h + (size_t)b * Nc * NHc;

    __shared__ float As[16][68];
    __shared__ float Bs[16][68];

    int tid = threadIdx.x;
    int ty = tid >> 4, tx = tid & 15;
    int ar = tid >> 2, ac = (tid & 3) * 4;       // A tile load: 64 rows x 16 cols
    int br = tid >> 4, bc = (tid & 15) * 4;      // B tile load: 16 rows x 64 cols

    float acc[4][4] = {};

    for (int k0 = 0; k0 < Nc; k0 += 16) {
        float4 av = *(const float4*)(Ab + (size_t)(m0 + ar) * Nc + k0 + ac);
        float4 bv = *(const float4*)(Bb + (size_t)(k0 + br) * NHc + n0 + bc);
        As[ac + 0][ar] = av.x; As[ac + 1][ar] = av.y;
        As[ac + 2][ar] = av.z; As[ac + 3][ar] = av.w;
        *(float4*)&Bs[br][bc] = bv;
        __syncthreads();
#pragma unroll
        for (int kk = 0; kk < 16; kk++) {
            float4 a  = *(float4*)&As[kk][ty * 4];
            float4 b4 = *(float4*)&Bs[kk][tx * 4];
            acc[0][0] += a.x * b4.x; acc[0][1] += a.x * b4.y; acc[0][2] += a.x * b4.z; acc[0][3] += a.x * b4.w;
            acc[1][0] += a.y * b4.x; acc[1][1] += a.y * b4.y; acc[1][2] += a.y * b4.z; acc[1][3] += a.y * b4.w;
            acc[2][0] += a.z * b4.x; acc[2][1] += a.z * b4.y; acc[2][2] += a.z * b4.z; acc[2][3] += a.z * b4.w;
            acc[3][0] += a.w * b4.x; acc[3][1] += a.w * b4.y; acc[3][2] += a.w * b4.z; acc[3][3] += a.w * b4.w;
        }
        __syncthreads();
    }
    float* C = g_Hagg + (size_t)b * Nc * NHc;
#pragma unroll
    for (int im = 0; im < 4; im++) {
        float4 v = make_float4(acc[im][0], acc[im][1], acc[im][2], acc[im][3]);
        *(float4*)(C + (size_t)(m0 + ty * 4 + im) * NHc + n0 + tx * 4) = v;
    }
}

// ---------------------------------------------------------------------------
// G = [es | H | h_prev] @ Wbig + bbig      (4096 x 512, K = 384)
// Same tiling; A source switches per 16-wide k-chunk (chunks stay within one src).
// grid = 64 mtiles * 8 ntiles = 512 blocks
// ---------------------------------------------------------------------------
__global__ void k_gemmG(int hin) {
    const float* __restrict__ hprev = g_h[hin];
    int bx = blockIdx.x;
    int m0 = (bx >> 3) * 64;
    int n0 = (bx & 7) * 64;

    __shared__ float As[16][68];
    __shared__ float Bs[16][68];

    int tid = threadIdx.x;
    int ty = tid >> 4, tx = tid & 15;
    int ar = tid >> 2, ac = (tid & 3) * 4;
    int br = tid >> 4, bc = (tid & 15) * 4;

    float acc[4][4] = {};

    for (int k0 = 0; k0 < 384; k0 += 16) {
        const float* src = (k0 < 128) ? g_es : (k0 < 256) ? g_Hagg : hprev;
        int kloc = k0 & 127;
        float4 av = *(const float4*)(src + (size_t)(m0 + ar) * 128 + kloc + ac);
        float4 bv = *(const float4*)(g_Wbig + (size_t)(k0 + br) * 512 + n0 + bc);
        As[ac + 0][ar] = av.x; As[ac + 1][ar] = av.y;
        As[ac + 2][ar] = av.z; As[ac + 3][ar] = av.w;
        *(float4*)&Bs[br][bc] = bv;
        __syncthreads();
#pragma unroll
        for (int kk = 0; kk < 16; kk++) {
            float4 a  = *(float4*)&As[kk][ty * 4];
            float4 b4 = *(float4*)&Bs[kk][tx * 4];
            acc[0][0] += a.x * b4.x; acc[0][1] += a.x * b4.y; acc[0][2] += a.x * b4.z; acc[0][3] += a.x * b4.w;
            acc[1][0] += a.y * b4.x; acc[1][1] += a.y * b4.y; acc[1][2] += a.y * b4.z; acc[1][3] += a.y * b4.w;
            acc[2][0] += a.z * b4.x; acc[2][1] += a.z * b4.y; acc[2][2] += a.z * b4.z; acc[2][3] += a.z * b4.w;
            acc[3][0] += a.w * b4.x; acc[3][1] += a.w * b4.y; acc[3][2] += a.w * b4.z; acc[3][3] += a.w * b4.w;
        }
        __syncthreads();
    }
#pragma unroll
    for (int im = 0; im < 4; im++) {
        int m = m0 + ty * 4 + im;
        int n = n0 + tx * 4;
        float4 bb = *(const float4*)(g_bbig + n);
        float4 v = make_float4(acc[im][0] + bb.x, acc[im][1] + bb.y,
                               acc[im][2] + bb.z, acc[im][3] + bb.w);
        *(float4*)(g_G + (size_t)m * 512 + n) = v;
    }
}

// ---------------------------------------------------------------------------
// Elementwise LSTM update + Xi += h_new @ Wout + bout ; write out[:, :, t, :]
// Block = 16 rows, 256 threads, 256 blocks.
// ---------------------------------------------------------------------------
__global__ void k_update(int hout, int t, const float* __restrict__ Wout,
                         const float* __restrict__ bout, float* __restrict__ out) {
    __shared__ float Ws[128 * 64];   // 32 KB
    __shared__ float hs[16][128];    // 8 KB
    int tid = threadIdx.x;
    int row0 = blockIdx.x * 16;

    for (int i = tid; i < 128 * 64; i += 256) Ws[i] = Wout[i];

    // phase 1: gates + state update
    {
        int r  = tid >> 4;
        int cb = (tid & 15) * 8;
        int row = row0 + r;
        const float* Grow = g_G + (size_t)row * 512;
        float* hO = g_h[hout];
#pragma unroll
        for (int q = 0; q < 8; q++) {
            int j = cb + q;
            float iv = 1.f / (1.f + expf(-Grow[j]));
            float fv = 1.f / (1.f + expf(-Grow[128 + j]));
            float gv = tanhf(Grow[256 + j]);
            float ov = 1.f / (1.f + expf(-Grow[384 + j]));
            float c = fv * g_c[row * 128 + j] + iv * gv;
            g_c[row * 128 + j] = c;
            float hv = ov * tanhf(c);
            hO[(size_t)row * 128 + j] = hv;
            hs[r][j] = hv;
        }
    }
    __syncthreads();

    // phase 2: Xi += h @ Wout + bout ; emit out[b,n,t,:]
#pragma unroll
    for (int kq = 0; kq < 4; kq++) {
        int e  = tid + kq * 256;
        int rr = e >> 6;
        int d  = e & 63;
        int grow = row0 + rr;
        float acc = g_Xi[grow * 64 + d] + bout[d];
#pragma unroll 8
        for (int kk = 0; kk < 128; kk++) acc += hs[rr][kk] * Ws[kk * 64 + d];
        g_Xi[grow * 64 + d] = acc;
        out[(size_t)grow * 4096 + t * 64 + d] = acc;
    }
}

// ---------------------------------------------------------------------------
extern "C" void kernel_launch(void* const* d_in, const int* in_sizes, int n_in,
                              void* d_out, int out_size) {
    const float* X    = (const float*)d_in[0];
    const float* A    = (const float*)d_in[1];
    const float* Wse  = (const float*)d_in[2];
    const float* bse  = (const float*)d_in[3];
    const float* Wpe  = (const float*)d_in[4];
    const float* bpe  = (const float*)d_in[5];
    const float* Wii  = (const float*)d_in[6];
    const float* bii  = (const float*)d_in[7];
    const float* Whi  = (const float*)d_in[8];
    const float* bhi  = (const float*)d_in[9];
    const float* Wif  = (const float*)d_in[10];
    const float* bif_ = (const float*)d_in[11];
    const float* Whf  = (const float*)d_in[12];
    const float* bhf  = (const float*)d_in[13];
    const float* Wig  = (const float*)d_in[14];
    const float* big_ = (const float*)d_in[15];
    const float* Whg  = (const float*)d_in[16];
    const float* bhg  = (const float*)d_in[17];
    const float* Wio  = (const float*)d_in[18];
    const float* bio  = (const float*)d_in[19];
    const float* Who  = (const float*)d_in[20];
    const float* bho  = (const float*)d_in[21];
    const float* Wout = (const float*)d_in[22];
    const float* bout = (const float*)d_in[23];
    float* out = (float*)d_out;

    k_dinv<<<Rc, 128>>>(A);
    k_an<<<2048, 256>>>(A);
    k_prep<<<512, 128>>>(Wii, bii, Whi, bhi, Wif, bif_, Whf, bhf,
                         Wig, big_, Whg, bhg, Wio, bio, Who, bho, Wpe, bpe);
    k_init<<<Rc, 128>>>(X, Wse, bse, out);

    for (int t = 1; t < Tc; t++) {
        int hin  = (t - 1) & 1;
        int hout = t & 1;
        k_gemmH<<<128, 256>>>(hin);
        k_gemmG<<<512, 256>>>(hin);
        k_update<<<256, 256>>>(hout, t, Wout, bout, out);
    }
}